// round 1
// baseline (speedup 1.0000x reference)
#include <cuda_runtime.h>
#include <math.h>

#define NMAX 100000
#define EMAX 1600000
#define HEADS 4
#define HID 32
#define F1 128
#define IN_NODE 12
#define IN_GLB 11
#define IN1 23
#define EDGE_DIM 5
#define DEC_IN 69
#define DEC_H1 64
#define DEC_H2 32
#define DEC_OUT 4

__device__ float g_g[NMAX * F1];
__device__ float g_h1[NMAX * F1];
__device__ float g_h2[NMAX * HID];
__device__ float g_als[NMAX * HEADS];
__device__ float g_ald[NMAX * HEADS];
__device__ int   g_cnt[NMAX];
__device__ int   g_off[NMAX + 1];
__device__ int   g_cur[NMAX];
__device__ int   g_srcs[EMAX];
__device__ float g_t1[F1];
__device__ float g_w1tt[IN_NODE * F1];
__device__ float g_w1t[DEC_IN * DEC_H1];
__device__ float g_w2t[DEC_H1 * DEC_H2];

__device__ __forceinline__ float lrelu02(float x) { return x > 0.f ? x : 0.2f * x; }
__device__ __forceinline__ float eluf(float x)    { return x > 0.f ? x : expm1f(x); }

__global__ void k_prep(const float* __restrict__ u, const float* __restrict__ W1,
                       const float* __restrict__ dw1, const float* __restrict__ dw2) {
    int tid = threadIdx.x;
    if (tid < F1) {
        float s = 0.f;
        #pragma unroll
        for (int k = 0; k < IN_GLB; k++) s += u[k] * W1[tid * IN1 + IN_NODE + k];
        g_t1[tid] = s;
    }
    for (int i = tid; i < IN_NODE * F1; i += blockDim.x) {
        int k = i >> 7, f = i & 127;
        g_w1tt[i] = W1[f * IN1 + k];
    }
    for (int i = tid; i < DEC_IN * DEC_H1; i += blockDim.x) {
        int k = i / DEC_H1, o = i - k * DEC_H1;
        g_w1t[i] = dw1[o * DEC_IN + k];
    }
    for (int i = tid; i < DEC_H1 * DEC_H2; i += blockDim.x) {
        int k = i >> 5, o = i & 31;
        g_w2t[i] = dw2[o * DEC_H1 + k];
    }
}

__global__ void k_gemm1(const float* __restrict__ x,
                        const float* __restrict__ asrc, const float* __restrict__ adst,
                        int N) {
    int n0 = blockIdx.x * 4;
    int f = threadIdx.x;
    __shared__ float xs[4][IN_NODE];
    if (f < 4 * IN_NODE) {
        int i = f / IN_NODE, k = f - i * IN_NODE;
        int n = n0 + i;
        xs[i][k] = (n < N) ? x[n * IN_NODE + k] : 0.f;
    }
    __syncthreads();
    float acc[4];
    float t = g_t1[f];
    #pragma unroll
    for (int i = 0; i < 4; i++) acc[i] = t;
    #pragma unroll
    for (int k = 0; k < IN_NODE; k++) {
        float w = g_w1tt[k * F1 + f];
        #pragma unroll
        for (int i = 0; i < 4; i++) acc[i] += xs[i][k] * w;
    }
    int h = f >> 5;
    float cas = asrc[f], cad = adst[f];
    #pragma unroll
    for (int i = 0; i < 4; i++) {
        int n = n0 + i;
        if (n >= N) break;
        g_g[n * F1 + f] = acc[i];
        float vs = acc[i] * cas, vd = acc[i] * cad;
        #pragma unroll
        for (int o = 16; o; o >>= 1) {
            vs += __shfl_xor_sync(0xffffffffu, vs, o);
            vd += __shfl_xor_sync(0xffffffffu, vd, o);
        }
        if ((f & 31) == 0) {
            g_als[n * HEADS + h] = vs;
            g_ald[n * HEADS + h] = vd;
        }
    }
}

__global__ void k_gemm2(const float* __restrict__ W2,
                        const float* __restrict__ asrc, const float* __restrict__ adst,
                        int N) {
    int n0 = blockIdx.x * 4;
    int f = threadIdx.x;
    __shared__ __align__(16) float hs[4][F1];
    #pragma unroll
    for (int i = 0; i < 4; i++) {
        int n = n0 + i;
        hs[i][f] = (n < N) ? g_h1[n * F1 + f] : 0.f;
    }
    __syncthreads();
    float acc[4] = {0.f, 0.f, 0.f, 0.f};
    const float4* wrow = reinterpret_cast<const float4*>(W2 + f * F1);
    #pragma unroll
    for (int k = 0; k < F1 / 4; k++) {
        float4 wv = wrow[k];
        #pragma unroll
        for (int i = 0; i < 4; i++) {
            float4 hv = *reinterpret_cast<const float4*>(&hs[i][4 * k]);
            acc[i] += wv.x * hv.x + wv.y * hv.y + wv.z * hv.z + wv.w * hv.w;
        }
    }
    int h = f >> 5;
    float cas = asrc[f], cad = adst[f];
    #pragma unroll
    for (int i = 0; i < 4; i++) {
        int n = n0 + i;
        if (n >= N) break;
        g_g[n * F1 + f] = acc[i];
        float vs = acc[i] * cas, vd = acc[i] * cad;
        #pragma unroll
        for (int o = 16; o; o >>= 1) {
            vs += __shfl_xor_sync(0xffffffffu, vs, o);
            vd += __shfl_xor_sync(0xffffffffu, vd, o);
        }
        if ((f & 31) == 0) {
            g_als[n * HEADS + h] = vs;
            g_ald[n * HEADS + h] = vd;
        }
    }
}

__global__ void k_zero(int N) {
    int i = blockIdx.x * blockDim.x + threadIdx.x;
    if (i < N) g_cnt[i] = 0;
}
__global__ void k_hist(const int* __restrict__ dst, int M) {
    int e = blockIdx.x * blockDim.x + threadIdx.x;
    if (e < M) atomicAdd(&g_cnt[dst[e]], 1);
}
__global__ void k_scan(int N) {
    __shared__ int sh[1024];
    __shared__ int carry_s;
    int tid = threadIdx.x;
    if (tid == 0) carry_s = 0;
    __syncthreads();
    for (int base = 0; base < N; base += 1024) {
        int i = base + tid;
        int v = (i < N) ? g_cnt[i] : 0;
        sh[tid] = v;
        __syncthreads();
        for (int o = 1; o < 1024; o <<= 1) {
            int t = (tid >= o) ? sh[tid - o] : 0;
            __syncthreads();
            sh[tid] += t;
            __syncthreads();
        }
        int incl = sh[tid];
        int carry = carry_s;
        if (i < N) g_off[i] = carry + incl - v;
        __syncthreads();
        if (tid == 1023) carry_s = carry + incl;
        __syncthreads();
    }
    if (tid == 0) g_off[N] = carry_s;
}
__global__ void k_initcur(int N) {
    int i = blockIdx.x * blockDim.x + threadIdx.x;
    if (i < N) g_cur[i] = g_off[i];
}
__global__ void k_scatter(const int* __restrict__ src, const int* __restrict__ dst, int M) {
    int e = blockIdx.x * blockDim.x + threadIdx.x;
    if (e < M) {
        int d = dst[e];
        int p = atomicAdd(&g_cur[d], 1);
        g_srcs[p] = src[e];
    }
}

// concat==1 -> write h1[n,128] (bias b, ELU); concat==0 -> mean heads -> h2[n,32]
__global__ void k_agg(const float* __restrict__ bias, int concat, int N) {
    int n = blockIdx.x;
    if (n >= N) return;
    int h = threadIdx.x >> 5;
    int lane = threadIdx.x & 31;
    int beg = g_off[n], end = g_off[n + 1];

    float ad = g_ald[n * HEADS + h];
    float es = lrelu02(g_als[n * HEADS + h] + ad);

    float m = es;
    for (int j = beg + lane; j < end; j += 32) {
        int s = g_srcs[j];
        m = fmaxf(m, lrelu02(g_als[s * HEADS + h] + ad));
    }
    #pragma unroll
    for (int o = 16; o; o >>= 1) m = fmaxf(m, __shfl_xor_sync(0xffffffffu, m, o));

    float ws = expf(es - m);
    float acc = ws * g_g[n * F1 + (h << 5) + lane];
    float psum = 0.f;
    for (int base = beg; base < end; base += 32) {
        int j = base + lane;
        float w = 0.f;
        int s = 0;
        if (j < end) {
            s = g_srcs[j];
            w = expf(lrelu02(g_als[s * HEADS + h] + ad) - m);
            psum += w;
        }
        int lim = min(32, end - base);
        for (int kk = 0; kk < lim; kk++) {
            float wk = __shfl_sync(0xffffffffu, w, kk);
            int sk = __shfl_sync(0xffffffffu, s, kk);
            acc += wk * g_g[sk * F1 + (h << 5) + lane];
        }
    }
    #pragma unroll
    for (int o = 16; o; o >>= 1) psum += __shfl_xor_sync(0xffffffffu, psum, o);
    float v = acc / (psum + ws);

    if (concat) {
        v += bias[(h << 5) + lane];
        g_h1[n * F1 + (h << 5) + lane] = eluf(v);
    } else {
        __shared__ float sm[F1];
        sm[(h << 5) + lane] = v;
        __syncthreads();
        if (h == 0) {
            float t = (sm[lane] + sm[32 + lane] + sm[64 + lane] + sm[96 + lane]) * 0.25f
                      + bias[lane];
            g_h2[n * HID + lane] = eluf(t);
        }
    }
}

#define TB 32
#define OF_SW1 0
#define OF_SW2 4416
#define OF_SW3 6464
#define OF_SB1 6592
#define OF_SB2 6656
#define OF_SB3 6688
#define OF_SRC 6692
#define OF_DST 6724
#define OF_EIN 6756
#define OF_Z1  9034
#define OF_Z2  11210
#define POOL_F 12272

__global__ __launch_bounds__(256) void k_dec(
    const int* __restrict__ ei, const float* __restrict__ eattr,
    const float* __restrict__ db1, const float* __restrict__ db2,
    const float* __restrict__ dw3, const float* __restrict__ db3,
    float* __restrict__ out, int M) {
    __shared__ __align__(16) float P[POOL_F];
    int tid = threadIdx.x;
    float* sw1 = P + OF_SW1;
    float* sw2 = P + OF_SW2;
    float* sw3 = P + OF_SW3;
    float* sb1 = P + OF_SB1;
    float* sb2 = P + OF_SB2;
    float* sb3 = P + OF_SB3;
    int* ssrc = reinterpret_cast<int*>(P + OF_SRC);
    int* sdst = reinterpret_cast<int*>(P + OF_DST);
    float* ein = P + OF_EIN;
    float* z1t = P + OF_Z1;
    float* z2t = P + OF_Z2;

    for (int i = tid; i < DEC_IN * DEC_H1; i += 256) sw1[i] = g_w1t[i];
    for (int i = tid; i < DEC_H1 * DEC_H2; i += 256) sw2[i] = g_w2t[i];
    if (tid < 128) sw3[tid] = dw3[tid];
    if (tid < 64) sb1[tid] = db1[tid];
    if (tid < 32) sb2[tid] = db2[tid];
    if (tid < 4)  sb3[tid] = db3[tid];

    const int* srcp = ei;
    const int* dstp = ei + M;
    int ntiles = (M + TB - 1) / TB;
    int tx = tid & 15, ty = tid >> 4;

    for (int tile = blockIdx.x; tile < ntiles; tile += gridDim.x) {
        int e0 = tile * TB;
        int nE = min(TB, M - e0);
        __syncthreads();
        if (tid < TB) {
            ssrc[tid] = (tid < nE) ? srcp[e0 + tid] : 0;
            sdst[tid] = (tid < nE) ? dstp[e0 + tid] : 0;
        }
        __syncthreads();
        for (int i = tid; i < TB * HID; i += 256) {
            int e = i >> 5, k = i & 31;
            ein[k * 33 + e] = g_h2[ssrc[e] * HID + k];
            ein[(HID + k) * 33 + e] = g_h2[sdst[e] * HID + k];
        }
        for (int i = tid; i < TB * EDGE_DIM; i += 256) {
            int e = i / EDGE_DIM, k = i - e * EDGE_DIM;
            int ge = e0 + e;
            ein[(2 * HID + k) * 33 + e] = (ge < M) ? eattr[ge * EDGE_DIM + k] : 0.f;
        }
        __syncthreads();

        float a[2][4];
        #pragma unroll
        for (int i = 0; i < 2; i++)
            #pragma unroll
            for (int j = 0; j < 4; j++) a[i][j] = 0.f;
        #pragma unroll 3
        for (int k = 0; k < DEC_IN; k++) {
            float e0v = ein[k * 33 + ty * 2];
            float e1v = ein[k * 33 + ty * 2 + 1];
            float4 wv = *reinterpret_cast<const float4*>(&sw1[k * DEC_H1 + tx * 4]);
            a[0][0] += e0v * wv.x; a[0][1] += e0v * wv.y; a[0][2] += e0v * wv.z; a[0][3] += e0v * wv.w;
            a[1][0] += e1v * wv.x; a[1][1] += e1v * wv.y; a[1][2] += e1v * wv.z; a[1][3] += e1v * wv.w;
        }
        #pragma unroll
        for (int j = 0; j < 4; j++) {
            float b = sb1[tx * 4 + j];
            #pragma unroll
            for (int i = 0; i < 2; i++) {
                float v = a[i][j] + b;
                z1t[(tx * 4 + j) * 34 + ty * 2 + i] = fmaxf(v, 0.f);
            }
        }
        __syncthreads();

        float b2a[2][2] = {{0.f, 0.f}, {0.f, 0.f}};
        #pragma unroll 4
        for (int k = 0; k < DEC_H1; k++) {
            float2 zv = *reinterpret_cast<const float2*>(&z1t[k * 34 + ty * 2]);
            float2 wv = *reinterpret_cast<const float2*>(&sw2[k * DEC_H2 + tx * 2]);
            b2a[0][0] += zv.x * wv.x; b2a[0][1] += zv.x * wv.y;
            b2a[1][0] += zv.y * wv.x; b2a[1][1] += zv.y * wv.y;
        }
        #pragma unroll
        for (int j = 0; j < 2; j++) {
            float b = sb2[tx * 2 + j];
            #pragma unroll
            for (int i = 0; i < 2; i++) {
                float v = b2a[i][j] + b;
                z2t[(tx * 2 + j) * 33 + ty * 2 + i] = fmaxf(v, 0.f);
            }
        }
        __syncthreads();

        if (tid < 128) {
            int e = tid >> 2, o = tid & 3;
            float acc = sb3[o];
            #pragma unroll
            for (int k = 0; k < DEC_H2; k++) acc += z2t[k * 33 + e] * sw3[o * DEC_H2 + k];
            if (e < nE) out[(e0 + e) * DEC_OUT + o] = acc;
        }
    }
}

extern "C" void kernel_launch(void* const* d_in, const int* in_sizes, int n_in,
                              void* d_out, int out_size) {
    const float* x     = (const float*)d_in[0];
    const int*   ei    = (const int*)d_in[1];
    const float* eattr = (const float*)d_in[2];
    const float* u     = (const float*)d_in[3];
    const float* W1    = (const float*)d_in[4];
    const float* as1   = (const float*)d_in[5];
    const float* ad1   = (const float*)d_in[6];
    const float* b1    = (const float*)d_in[7];
    const float* W2    = (const float*)d_in[8];
    const float* as2   = (const float*)d_in[9];
    const float* ad2   = (const float*)d_in[10];
    const float* b2    = (const float*)d_in[11];
    const float* dw1   = (const float*)d_in[12];
    const float* db1   = (const float*)d_in[13];
    const float* dw2   = (const float*)d_in[14];
    const float* db2   = (const float*)d_in[15];
    const float* dw3   = (const float*)d_in[16];
    const float* db3   = (const float*)d_in[17];
    float* out = (float*)d_out;

    int N = in_sizes[0] / IN_NODE;
    int M = in_sizes[1] / 2;
    if (N > NMAX || M > EMAX || N <= 0 || M <= 0) return;

    const int* srcp = ei;
    const int* dstp = ei + M;

    k_zero<<<(N + 255) / 256, 256>>>(N);
    k_prep<<<1, 256>>>(u, W1, dw1, dw2);
    k_hist<<<(M + 255) / 256, 256>>>(dstp, M);
    k_scan<<<1, 1024>>>(N);
    k_initcur<<<(N + 255) / 256, 256>>>(N);
    k_scatter<<<(M + 255) / 256, 256>>>(srcp, dstp, M);

    k_gemm1<<<(N + 3) / 4, 128>>>(x, as1, ad1, N);
    k_agg<<<N, 128>>>(b1, 1, N);

    k_gemm2<<<(N + 3) / 4, 128>>>(W2, as2, ad2, N);
    k_agg<<<N, 128>>>(b2, 0, N);

    k_dec<<<592, 256>>>(ei, eattr, db1, db2, dw3, db3, out, M);
}

// round 2
// speedup vs baseline: 1.4255x; 1.4255x over previous
#include <cuda_runtime.h>
#include <math.h>

#define NMAX 100000
#define EMAX 1600000
#define HEADS 4
#define HID 32
#define F1 128
#define IN_NODE 12
#define IN_GLB 11
#define IN1 23
#define EDGE_DIM 5
#define DEC_IN 69
#define DEC_H1 64
#define DEC_H2 32
#define DEC_OUT 4

__device__ float g_g[NMAX * F1];
__device__ float g_h1[NMAX * F1];
__device__ float g_h2[NMAX * HID];
__device__ float g_pa[NMAX * DEC_H1];
__device__ float g_pb[NMAX * DEC_H1];
__device__ float g_als[NMAX * HEADS];
__device__ float g_ald[NMAX * HEADS];
__device__ int   g_cnt[NMAX];
__device__ int   g_off[NMAX + 1];
__device__ int   g_cur[NMAX];
__device__ int   g_srcs[EMAX];
__device__ int   g_bsum[128];
__device__ int   g_bsumx[128];
__device__ float g_t1[F1];
__device__ float g_w1tt[IN_NODE * F1];
__device__ float g_w2t[DEC_H1 * DEC_H2];

__device__ __forceinline__ float lrelu02(float x) { return x > 0.f ? x : 0.2f * x; }
__device__ __forceinline__ float eluf(float x)    { return x > 0.f ? x : expm1f(x); }

// ---------------- prep: t1 (u @ W1 global part), transposes ----------------
__global__ void k_prep(const float* __restrict__ u, const float* __restrict__ W1,
                       const float* __restrict__ dw2) {
    int tid = threadIdx.x;
    if (tid < F1) {
        float s = 0.f;
        #pragma unroll
        for (int k = 0; k < IN_GLB; k++) s += u[k] * W1[tid * IN1 + IN_NODE + k];
        g_t1[tid] = s;
    }
    for (int i = tid; i < IN_NODE * F1; i += blockDim.x) {
        int k = i >> 7, f = i & 127;
        g_w1tt[i] = W1[f * IN1 + k];
    }
    for (int i = tid; i < DEC_H1 * DEC_H2; i += blockDim.x) {
        int k = i >> 5, o = i & 31;
        g_w2t[i] = dw2[o * DEC_H1 + k];
    }
}

// ---------------- layer-1 node transform + attention logits ----------------
__global__ void k_gemm1(const float* __restrict__ x,
                        const float* __restrict__ asrc, const float* __restrict__ adst,
                        int N) {
    int n0 = blockIdx.x * 4;
    int f = threadIdx.x;
    __shared__ float xs[4][IN_NODE];
    if (f < 4 * IN_NODE) {
        int i = f / IN_NODE, k = f - i * IN_NODE;
        int n = n0 + i;
        xs[i][k] = (n < N) ? x[n * IN_NODE + k] : 0.f;
    }
    __syncthreads();
    float acc[4];
    float t = g_t1[f];
    #pragma unroll
    for (int i = 0; i < 4; i++) acc[i] = t;
    #pragma unroll
    for (int k = 0; k < IN_NODE; k++) {
        float w = g_w1tt[k * F1 + f];
        #pragma unroll
        for (int i = 0; i < 4; i++) acc[i] += xs[i][k] * w;
    }
    int h = f >> 5;
    float cas = asrc[f], cad = adst[f];
    #pragma unroll
    for (int i = 0; i < 4; i++) {
        int n = n0 + i;
        if (n >= N) break;
        g_g[n * F1 + f] = acc[i];
        float vs = acc[i] * cas, vd = acc[i] * cad;
        #pragma unroll
        for (int o = 16; o; o >>= 1) {
            vs += __shfl_xor_sync(0xffffffffu, vs, o);
            vd += __shfl_xor_sync(0xffffffffu, vd, o);
        }
        if ((f & 31) == 0) {
            g_als[n * HEADS + h] = vs;
            g_ald[n * HEADS + h] = vd;
        }
    }
}

// ---------------- layer-2 node transform + attention logits ----------------
__global__ void k_gemm2(const float* __restrict__ W2,
                        const float* __restrict__ asrc, const float* __restrict__ adst,
                        int N) {
    int n0 = blockIdx.x * 4;
    int f = threadIdx.x;
    __shared__ __align__(16) float hs[4][F1];
    #pragma unroll
    for (int i = 0; i < 4; i++) {
        int n = n0 + i;
        hs[i][f] = (n < N) ? g_h1[n * F1 + f] : 0.f;
    }
    __syncthreads();
    float acc[4] = {0.f, 0.f, 0.f, 0.f};
    const float4* wrow = reinterpret_cast<const float4*>(W2 + f * F1);
    #pragma unroll
    for (int k = 0; k < F1 / 4; k++) {
        float4 wv = wrow[k];
        #pragma unroll
        for (int i = 0; i < 4; i++) {
            float4 hv = *reinterpret_cast<const float4*>(&hs[i][4 * k]);
            acc[i] += wv.x * hv.x + wv.y * hv.y + wv.z * hv.z + wv.w * hv.w;
        }
    }
    int h = f >> 5;
    float cas = asrc[f], cad = adst[f];
    #pragma unroll
    for (int i = 0; i < 4; i++) {
        int n = n0 + i;
        if (n >= N) break;
        g_g[n * F1 + f] = acc[i];
        float vs = acc[i] * cas, vd = acc[i] * cad;
        #pragma unroll
        for (int o = 16; o; o >>= 1) {
            vs += __shfl_xor_sync(0xffffffffu, vs, o);
            vd += __shfl_xor_sync(0xffffffffu, vd, o);
        }
        if ((f & 31) == 0) {
            g_als[n * HEADS + h] = vs;
            g_ald[n * HEADS + h] = vd;
        }
    }
}

// ---------------- CSR build (multi-block scan) ------------------------------
__global__ void k_zero(int N) {
    int i = blockIdx.x * blockDim.x + threadIdx.x;
    if (i < N) g_cnt[i] = 0;
}
__global__ void k_hist(const int* __restrict__ dst, int M) {
    int e = blockIdx.x * blockDim.x + threadIdx.x;
    if (e < M) atomicAdd(&g_cnt[dst[e]], 1);
}
__global__ void k_scan1(int N) {
    __shared__ int sh[1024];
    int tid = threadIdx.x;
    int i = blockIdx.x * 1024 + tid;
    int v = (i < N) ? g_cnt[i] : 0;
    sh[tid] = v;
    __syncthreads();
    for (int o = 1; o < 1024; o <<= 1) {
        int t = (tid >= o) ? sh[tid - o] : 0;
        __syncthreads();
        sh[tid] += t;
        __syncthreads();
    }
    if (i < N) g_off[i] = sh[tid] - v;   // block-local exclusive
    if (tid == 1023) g_bsum[blockIdx.x] = sh[1023];
}
__global__ void k_scan2(int nb, int N, int M) {
    __shared__ int sh[128];
    int tid = threadIdx.x;
    int v = (tid < nb) ? g_bsum[tid] : 0;
    sh[tid] = v;
    __syncthreads();
    for (int o = 1; o < 128; o <<= 1) {
        int t = (tid >= o) ? sh[tid - o] : 0;
        __syncthreads();
        sh[tid] += t;
        __syncthreads();
    }
    if (tid < nb) g_bsumx[tid] = sh[tid] - v;
    if (tid == 0) g_off[N] = M;
}
__global__ void k_scan3(int N) {
    int i = blockIdx.x * blockDim.x + threadIdx.x;
    if (i < N) {
        int v = g_off[i] + g_bsumx[i >> 10];
        g_off[i] = v;
        g_cur[i] = v;
    }
}
__global__ void k_scatter(const int* __restrict__ src, const int* __restrict__ dst, int M) {
    int e = blockIdx.x * blockDim.x + threadIdx.x;
    if (e < M) {
        int d = dst[e];
        int p = atomicAdd(&g_cur[d], 1);
        g_srcs[p] = src[e];
    }
}

// ---------------- GAT aggregation (softmax + weighted sum + self-loop) -----
__global__ void k_agg(const float* __restrict__ bias, int concat, int N) {
    int n = blockIdx.x;
    if (n >= N) return;
    int h = threadIdx.x >> 5;
    int lane = threadIdx.x & 31;
    int beg = g_off[n], end = g_off[n + 1];

    float ad = g_ald[n * HEADS + h];
    float es = lrelu02(g_als[n * HEADS + h] + ad);

    float m = es;
    for (int j = beg + lane; j < end; j += 32) {
        int s = g_srcs[j];
        m = fmaxf(m, lrelu02(g_als[s * HEADS + h] + ad));
    }
    #pragma unroll
    for (int o = 16; o; o >>= 1) m = fmaxf(m, __shfl_xor_sync(0xffffffffu, m, o));

    float ws = expf(es - m);
    float acc = ws * g_g[n * F1 + (h << 5) + lane];
    float psum = 0.f;
    for (int base = beg; base < end; base += 32) {
        int j = base + lane;
        float w = 0.f;
        int s = 0;
        if (j < end) {
            s = g_srcs[j];
            w = expf(lrelu02(g_als[s * HEADS + h] + ad) - m);
            psum += w;
        }
        int lim = min(32, end - base);
        for (int kk = 0; kk < lim; kk++) {
            float wk = __shfl_sync(0xffffffffu, w, kk);
            int sk = __shfl_sync(0xffffffffu, s, kk);
            acc += wk * g_g[sk * F1 + (h << 5) + lane];
        }
    }
    #pragma unroll
    for (int o = 16; o; o >>= 1) psum += __shfl_xor_sync(0xffffffffu, psum, o);
    float v = acc / (psum + ws);

    if (concat) {
        v += bias[(h << 5) + lane];
        g_h1[n * F1 + (h << 5) + lane] = eluf(v);
    } else {
        __shared__ float sm[F1];
        sm[(h << 5) + lane] = v;
        __syncthreads();
        if (h == 0) {
            float t = (sm[lane] + sm[32 + lane] + sm[64 + lane] + sm[96 + lane]) * 0.25f
                      + bias[lane];
            g_h2[n * HID + lane] = eluf(t);
        }
    }
}

// ---------------- decoder precompute: pa/pb = dw1 halves @ h2 ---------------
__global__ __launch_bounds__(256) void k_pab(const float* __restrict__ dw1, int N) {
    __shared__ float sdw[64 * 65];
    __shared__ float sh2[16 * 32];
    int tid = threadIdx.x;
    for (int i = tid; i < 64 * 64; i += 256) {
        int o = i >> 6, k = i & 63;
        sdw[o * 65 + k] = dw1[o * DEC_IN + k];
    }
    int n0 = blockIdx.x * 16;
    for (int i = tid; i < 16 * 32; i += 256) {
        int nl = i >> 5, k = i & 31;
        int n = n0 + nl;
        sh2[i] = (n < N) ? g_h2[n * HID + k] : 0.f;
    }
    __syncthreads();
    int o = tid & 63, ng = tid >> 6;
    float pa[4] = {0.f, 0.f, 0.f, 0.f}, pb[4] = {0.f, 0.f, 0.f, 0.f};
    #pragma unroll
    for (int k = 0; k < 32; k++) {
        float wa = sdw[o * 65 + k];
        float wb = sdw[o * 65 + 32 + k];
        #pragma unroll
        for (int j = 0; j < 4; j++) {
            float hv = sh2[(ng * 4 + j) * 32 + k];
            pa[j] += wa * hv;
            pb[j] += wb * hv;
        }
    }
    #pragma unroll
    for (int j = 0; j < 4; j++) {
        int n = n0 + ng * 4 + j;
        if (n < N) {
            g_pa[n * 64 + o] = pa[j];
            g_pb[n * 64 + o] = pb[j];
        }
    }
}

// ---------------- decoder: gather + fused MLP, 32-edge tiles ----------------
#define TB 32
__global__ __launch_bounds__(256) void k_dec(
    const int* __restrict__ ei, const float* __restrict__ eattr,
    const float* __restrict__ dw1, const float* __restrict__ db1,
    const float* __restrict__ db2, const float* __restrict__ dw3,
    const float* __restrict__ db3, float* __restrict__ out, int M) {
    __shared__ __align__(16) float sw2[DEC_H1 * DEC_H2];
    __shared__ float sw3[DEC_H2 * DEC_OUT];
    __shared__ float sb2[DEC_H2];
    __shared__ float sb3[DEC_OUT];
    __shared__ float sw1c[EDGE_DIM * 64];
    __shared__ float sdb1[64];
    __shared__ int ssrc[TB], sdst[TB];
    __shared__ float eat[TB * EDGE_DIM];
    __shared__ __align__(16) float z1t[DEC_H1 * 34];
    __shared__ float z2t[DEC_H2 * 33];
    int tid = threadIdx.x;

    for (int i = tid; i < DEC_H1 * DEC_H2; i += 256) sw2[i] = g_w2t[i];
    if (tid < 128) sw3[tid] = dw3[tid];
    if (tid < 64)  sdb1[tid] = db1[tid];
    if (tid < 32)  sb2[tid] = db2[tid];
    if (tid < 4)   sb3[tid] = db3[tid];
    for (int i = tid; i < EDGE_DIM * 64; i += 256) {
        int k = i >> 6, o = i & 63;
        sw1c[i] = dw1[o * DEC_IN + 64 + k];
    }

    const int* srcp = ei;
    const int* dstp = ei + M;
    int ntiles = (M + TB - 1) / TB;
    int tx = tid & 15, ty = tid >> 4;

    for (int tile = blockIdx.x; tile < ntiles; tile += gridDim.x) {
        int e0 = tile * TB;
        int nE = min(TB, M - e0);
        __syncthreads();
        if (tid < TB) {
            ssrc[tid] = (tid < nE) ? srcp[e0 + tid] : 0;
            sdst[tid] = (tid < nE) ? dstp[e0 + tid] : 0;
        }
        for (int i = tid; i < TB * EDGE_DIM; i += 256) {
            int gi = e0 * EDGE_DIM + i;
            eat[i] = (gi < M * EDGE_DIM) ? eattr[gi] : 0.f;
        }
        __syncthreads();

        // z1 = relu(pa[src] + pb[dst] + dw1c @ eattr + db1)
        for (int i = tid; i < TB * 64; i += 256) {
            int e = i >> 6, o = i & 63;
            float v = g_pa[(size_t)ssrc[e] * 64 + o] + g_pb[(size_t)sdst[e] * 64 + o]
                      + sdb1[o];
            #pragma unroll
            for (int k = 0; k < EDGE_DIM; k++) v += sw1c[k * 64 + o] * eat[e * EDGE_DIM + k];
            z1t[o * 34 + e] = fmaxf(v, 0.f);
        }
        __syncthreads();

        // z2 = relu(z1 @ dw2^T + db2): [32e x 32o], K=64
        float b2a[2][2] = {{0.f, 0.f}, {0.f, 0.f}};
        #pragma unroll 4
        for (int k = 0; k < DEC_H1; k++) {
            float2 zv = *reinterpret_cast<const float2*>(&z1t[k * 34 + ty * 2]);
            float2 wv = *reinterpret_cast<const float2*>(&sw2[k * DEC_H2 + tx * 2]);
            b2a[0][0] += zv.x * wv.x; b2a[0][1] += zv.x * wv.y;
            b2a[1][0] += zv.y * wv.x; b2a[1][1] += zv.y * wv.y;
        }
        #pragma unroll
        for (int j = 0; j < 2; j++) {
            float b = sb2[tx * 2 + j];
            #pragma unroll
            for (int i = 0; i < 2; i++) {
                float v = b2a[i][j] + b;
                z2t[(tx * 2 + j) * 33 + ty * 2 + i] = fmaxf(v, 0.f);
            }
        }
        __syncthreads();

        // out = z2 @ dw3^T + db3: [32e x 4o], K=32
        if (tid < 128) {
            int e = tid >> 2, o = tid & 3;
            float acc = sb3[o];
            #pragma unroll
            for (int k = 0; k < DEC_H2; k++) acc += z2t[k * 33 + e] * sw3[o * DEC_H2 + k];
            if (e < nE) out[(e0 + e) * DEC_OUT + o] = acc;
        }
    }
}

// ---------------- launch -----------------------------------------------------
extern "C" void kernel_launch(void* const* d_in, const int* in_sizes, int n_in,
                              void* d_out, int out_size) {
    const float* x     = (const float*)d_in[0];
    const int*   ei    = (const int*)d_in[1];
    const float* eattr = (const float*)d_in[2];
    const float* u     = (const float*)d_in[3];
    const float* W1    = (const float*)d_in[4];
    const float* as1   = (const float*)d_in[5];
    const float* ad1   = (const float*)d_in[6];
    const float* b1    = (const float*)d_in[7];
    const float* W2    = (const float*)d_in[8];
    const float* as2   = (const float*)d_in[9];
    const float* ad2   = (const float*)d_in[10];
    const float* b2    = (const float*)d_in[11];
    const float* dw1   = (const float*)d_in[12];
    const float* db1   = (const float*)d_in[13];
    const float* dw2   = (const float*)d_in[14];
    const float* db2   = (const float*)d_in[15];
    const float* dw3   = (const float*)d_in[16];
    const float* db3   = (const float*)d_in[17];
    float* out = (float*)d_out;

    int N = in_sizes[0] / IN_NODE;
    int M = in_sizes[1] / 2;
    if (N > NMAX || M > EMAX || N <= 0 || M <= 0) return;

    const int* srcp = ei;
    const int* dstp = ei + M;
    int nb = (N + 1023) / 1024;

    k_zero<<<(N + 255) / 256, 256>>>(N);
    k_prep<<<1, 256>>>(u, W1, dw2);
    k_hist<<<(M + 255) / 256, 256>>>(dstp, M);
    k_scan1<<<nb, 1024>>>(N);
    k_scan2<<<1, 128>>>(nb, N, M);
    k_scan3<<<(N + 255) / 256, 256>>>(N);
    k_scatter<<<(M + 255) / 256, 256>>>(srcp, dstp, M);

    k_gemm1<<<(N + 3) / 4, 128>>>(x, as1, ad1, N);
    k_agg<<<N, 128>>>(b1, 1, N);

    k_gemm2<<<(N + 3) / 4, 128>>>(W2, as2, ad2, N);
    k_agg<<<N, 128>>>(b2, 0, N);

    k_pab<<<(N + 15) / 16, 256>>>(dw1, N);
    k_dec<<<1184, 256>>>(ei, eattr, dw1, db1, db2, dw3, db3, out, M);
}

// round 3
// speedup vs baseline: 1.8082x; 1.2685x over previous
#include <cuda_runtime.h>
#include <math.h>

#define NMAX 100000
#define EMAX 1600000
#define HEADS 4
#define HID 32
#define F1 128
#define IN_NODE 12
#define IN_GLB 11
#define IN1 23
#define EDGE_DIM 5
#define DEC_IN 69
#define DEC_H1 64
#define DEC_H2 32
#define DEC_OUT 4

__device__ float g_g[NMAX * F1];
__device__ float g_h1[NMAX * F1];
__device__ float g_h2[NMAX * HID];
__device__ float g_pa[NMAX * DEC_H1];
__device__ float g_pb[NMAX * DEC_H1];
__device__ float g_als[NMAX * HEADS];
__device__ float g_ald[NMAX * HEADS];
__device__ int   g_cnt[NMAX];
__device__ int   g_off[NMAX + 1];
__device__ int   g_cur[NMAX];
__device__ int   g_srcs[EMAX];
__device__ int   g_bsum[128];
__device__ int   g_bsumx[128];
__device__ float g_t1[F1];
__device__ float g_w1tt[IN_NODE * F1];
__device__ float g_w2t[DEC_H1 * DEC_H2];

__device__ __forceinline__ float lrelu02(float x) { return x > 0.f ? x : 0.2f * x; }
__device__ __forceinline__ float eluf(float x)    { return x > 0.f ? x : expm1f(x); }

// ---------------- prep: t1 (u @ W1 global part), transposes ----------------
__global__ void k_prep(const float* __restrict__ u, const float* __restrict__ W1,
                       const float* __restrict__ dw2) {
    int tid = threadIdx.x;
    if (tid < F1) {
        float s = 0.f;
        #pragma unroll
        for (int k = 0; k < IN_GLB; k++) s += u[k] * W1[tid * IN1 + IN_NODE + k];
        g_t1[tid] = s;
    }
    for (int i = tid; i < IN_NODE * F1; i += blockDim.x) {
        int k = i >> 7, f = i & 127;
        g_w1tt[i] = W1[f * IN1 + k];
    }
    for (int i = tid; i < DEC_H1 * DEC_H2; i += blockDim.x) {
        int k = i >> 5, o = i & 31;
        g_w2t[i] = dw2[o * DEC_H1 + k];
    }
}

// ---------------- layer-1 node transform + attention logits ----------------
__global__ void k_gemm1(const float* __restrict__ x,
                        const float* __restrict__ asrc, const float* __restrict__ adst,
                        int N) {
    int n0 = blockIdx.x * 4;
    int f = threadIdx.x;
    __shared__ float xs[4][IN_NODE];
    if (f < 4 * IN_NODE) {
        int i = f / IN_NODE, k = f - i * IN_NODE;
        int n = n0 + i;
        xs[i][k] = (n < N) ? x[n * IN_NODE + k] : 0.f;
    }
    __syncthreads();
    float acc[4];
    float t = g_t1[f];
    #pragma unroll
    for (int i = 0; i < 4; i++) acc[i] = t;
    #pragma unroll
    for (int k = 0; k < IN_NODE; k++) {
        float w = g_w1tt[k * F1 + f];
        #pragma unroll
        for (int i = 0; i < 4; i++) acc[i] += xs[i][k] * w;
    }
    int h = f >> 5;
    float cas = asrc[f], cad = adst[f];
    #pragma unroll
    for (int i = 0; i < 4; i++) {
        int n = n0 + i;
        if (n >= N) break;
        g_g[n * F1 + f] = acc[i];
        float vs = acc[i] * cas, vd = acc[i] * cad;
        #pragma unroll
        for (int o = 16; o; o >>= 1) {
            vs += __shfl_xor_sync(0xffffffffu, vs, o);
            vd += __shfl_xor_sync(0xffffffffu, vd, o);
        }
        if ((f & 31) == 0) {
            g_als[n * HEADS + h] = vs;
            g_ald[n * HEADS + h] = vd;
        }
    }
}

// ---------------- layer-2 node transform (16 nodes/block) ------------------
#define G2N 16
__global__ __launch_bounds__(128) void k_gemm2(const float* __restrict__ W2,
                        const float* __restrict__ asrc, const float* __restrict__ adst,
                        int N) {
    int n0 = blockIdx.x * G2N;
    int f = threadIdx.x;
    __shared__ __align__(16) float hs[G2N][F1];
    #pragma unroll
    for (int i = 0; i < G2N; i++) {
        int n = n0 + i;
        hs[i][f] = (n < N) ? g_h1[n * F1 + f] : 0.f;
    }
    __syncthreads();
    float acc[G2N];
    #pragma unroll
    for (int i = 0; i < G2N; i++) acc[i] = 0.f;
    const float4* wrow = reinterpret_cast<const float4*>(W2 + f * F1);
    #pragma unroll 8
    for (int k = 0; k < F1 / 4; k++) {
        float4 wv = wrow[k];
        #pragma unroll
        for (int i = 0; i < G2N; i++) {
            float4 hv = *reinterpret_cast<const float4*>(&hs[i][4 * k]);
            acc[i] += wv.x * hv.x + wv.y * hv.y + wv.z * hv.z + wv.w * hv.w;
        }
    }
    int h = f >> 5;
    float cas = asrc[f], cad = adst[f];
    #pragma unroll
    for (int i = 0; i < G2N; i++) {
        int n = n0 + i;
        if (n >= N) break;
        g_g[n * F1 + f] = acc[i];
        float vs = acc[i] * cas, vd = acc[i] * cad;
        #pragma unroll
        for (int o = 16; o; o >>= 1) {
            vs += __shfl_xor_sync(0xffffffffu, vs, o);
            vd += __shfl_xor_sync(0xffffffffu, vd, o);
        }
        if ((f & 31) == 0) {
            g_als[n * HEADS + h] = vs;
            g_ald[n * HEADS + h] = vd;
        }
    }
}

// ---------------- CSR build (multi-block scan) ------------------------------
__global__ void k_zero(int N) {
    int i = blockIdx.x * blockDim.x + threadIdx.x;
    if (i < N) g_cnt[i] = 0;
}
__global__ void k_hist(const int* __restrict__ dst, int M) {
    int e = blockIdx.x * blockDim.x + threadIdx.x;
    if (e < M) atomicAdd(&g_cnt[dst[e]], 1);
}
__global__ void k_scan1(int N) {
    __shared__ int sh[1024];
    int tid = threadIdx.x;
    int i = blockIdx.x * 1024 + tid;
    int v = (i < N) ? g_cnt[i] : 0;
    sh[tid] = v;
    __syncthreads();
    for (int o = 1; o < 1024; o <<= 1) {
        int t = (tid >= o) ? sh[tid - o] : 0;
        __syncthreads();
        sh[tid] += t;
        __syncthreads();
    }
    if (i < N) g_off[i] = sh[tid] - v;
    if (tid == 1023) g_bsum[blockIdx.x] = sh[1023];
}
__global__ void k_scan2(int nb, int N, int M) {
    __shared__ int sh[128];
    int tid = threadIdx.x;
    int v = (tid < nb) ? g_bsum[tid] : 0;
    sh[tid] = v;
    __syncthreads();
    for (int o = 1; o < 128; o <<= 1) {
        int t = (tid >= o) ? sh[tid - o] : 0;
        __syncthreads();
        sh[tid] += t;
        __syncthreads();
    }
    if (tid < nb) g_bsumx[tid] = sh[tid] - v;
    if (tid == 0) g_off[N] = M;
}
__global__ void k_scan3(int N) {
    int i = blockIdx.x * blockDim.x + threadIdx.x;
    if (i < N) {
        int v = g_off[i] + g_bsumx[i >> 10];
        g_off[i] = v;
        g_cur[i] = v;
    }
}
__global__ void k_scatter(const int* __restrict__ src, const int* __restrict__ dst, int M) {
    int e = blockIdx.x * blockDim.x + threadIdx.x;
    if (e < M) {
        int d = dst[e];
        int p = atomicAdd(&g_cur[d], 1);
        g_srcs[p] = src[e];
    }
}

// ---------------- GAT aggregation: SINGLE PASS (no max; logits are small) --
__global__ void k_agg(const float* __restrict__ bias, int concat, int N) {
    int n = blockIdx.x;
    if (n >= N) return;
    int h = threadIdx.x >> 5;
    int lane = threadIdx.x & 31;
    int beg = g_off[n], end = g_off[n + 1];

    float ad = g_ald[n * HEADS + h];
    float ws = __expf(lrelu02(g_als[n * HEADS + h] + ad));   // self-loop weight

    float acc = ws * g_g[n * F1 + (h << 5) + lane];
    float psum = 0.f;
    for (int base = beg; base < end; base += 32) {
        int j = base + lane;
        float w = 0.f;
        int s = 0;
        if (j < end) {
            s = g_srcs[j];
            w = __expf(lrelu02(g_als[s * HEADS + h] + ad));
            psum += w;
        }
        int lim = min(32, end - base);
        for (int kk = 0; kk < lim; kk++) {
            float wk = __shfl_sync(0xffffffffu, w, kk);
            int sk = __shfl_sync(0xffffffffu, s, kk);
            acc += wk * g_g[sk * F1 + (h << 5) + lane];
        }
    }
    #pragma unroll
    for (int o = 16; o; o >>= 1) psum += __shfl_xor_sync(0xffffffffu, psum, o);
    float v = acc / (psum + ws);

    if (concat) {
        v += bias[(h << 5) + lane];
        g_h1[n * F1 + (h << 5) + lane] = eluf(v);
    } else {
        __shared__ float sm[F1];
        sm[(h << 5) + lane] = v;
        __syncthreads();
        if (h == 0) {
            float t = (sm[lane] + sm[32 + lane] + sm[64 + lane] + sm[96 + lane]) * 0.25f
                      + bias[lane];
            g_h2[n * HID + lane] = eluf(t);
        }
    }
}

// ---------------- decoder precompute: pa/pb = dw1 halves @ h2 ---------------
__global__ __launch_bounds__(256) void k_pab(const float* __restrict__ dw1, int N) {
    __shared__ float sdw[64 * 65];
    __shared__ float sh2[16 * 32];
    int tid = threadIdx.x;
    for (int i = tid; i < 64 * 64; i += 256) {
        int o = i >> 6, k = i & 63;
        sdw[o * 65 + k] = dw1[o * DEC_IN + k];
    }
    int n0 = blockIdx.x * 16;
    for (int i = tid; i < 16 * 32; i += 256) {
        int nl = i >> 5, k = i & 31;
        int n = n0 + nl;
        sh2[i] = (n < N) ? g_h2[n * HID + k] : 0.f;
    }
    __syncthreads();
    int o = tid & 63, ng = tid >> 6;
    float pa[4] = {0.f, 0.f, 0.f, 0.f}, pb[4] = {0.f, 0.f, 0.f, 0.f};
    #pragma unroll
    for (int k = 0; k < 32; k++) {
        float wa = sdw[o * 65 + k];
        float wb = sdw[o * 65 + 32 + k];
        #pragma unroll
        for (int j = 0; j < 4; j++) {
            float hv = sh2[(ng * 4 + j) * 32 + k];
            pa[j] += wa * hv;
            pb[j] += wb * hv;
        }
    }
    #pragma unroll
    for (int j = 0; j < 4; j++) {
        int n = n0 + ng * 4 + j;
        if (n < N) {
            g_pa[n * 64 + o] = pa[j];
            g_pb[n * 64 + o] = pb[j];
        }
    }
}

// ---------------- decoder: gather + fused MLP, 32-edge tiles ----------------
#define TB 32
__global__ __launch_bounds__(256) void k_dec(
    const int* __restrict__ ei, const float* __restrict__ eattr,
    const float* __restrict__ dw1, const float* __restrict__ db1,
    const float* __restrict__ db2, const float* __restrict__ dw3,
    const float* __restrict__ db3, float* __restrict__ out, int M) {
    __shared__ __align__(16) float sw2[DEC_H1 * DEC_H2];
    __shared__ float sw3[DEC_H2 * DEC_OUT];
    __shared__ float sb2[DEC_H2];
    __shared__ float sb3[DEC_OUT];
    __shared__ float sw1c[EDGE_DIM * 64];
    __shared__ float sdb1[64];
    __shared__ int ssrc[TB], sdst[TB];
    __shared__ float eat[TB * EDGE_DIM];
    __shared__ __align__(16) float z1t[DEC_H1 * 34];
    __shared__ float z2t[DEC_H2 * 33];
    int tid = threadIdx.x;

    for (int i = tid; i < DEC_H1 * DEC_H2; i += 256) sw2[i] = g_w2t[i];
    if (tid < 128) sw3[tid] = dw3[tid];
    if (tid < 64)  sdb1[tid] = db1[tid];
    if (tid < 32)  sb2[tid] = db2[tid];
    if (tid < 4)   sb3[tid] = db3[tid];
    for (int i = tid; i < EDGE_DIM * 64; i += 256) {
        int k = i >> 6, o = i & 63;
        sw1c[i] = dw1[o * DEC_IN + 64 + k];
    }

    const int* srcp = ei;
    const int* dstp = ei + M;
    int ntiles = (M + TB - 1) / TB;
    int tx = tid & 15, ty = tid >> 4;

    for (int tile = blockIdx.x; tile < ntiles; tile += gridDim.x) {
        int e0 = tile * TB;
        int nE = min(TB, M - e0);
        __syncthreads();
        if (tid < TB) {
            ssrc[tid] = (tid < nE) ? srcp[e0 + tid] : 0;
            sdst[tid] = (tid < nE) ? dstp[e0 + tid] : 0;
        }
        for (int i = tid; i < TB * EDGE_DIM; i += 256) {
            int gi = e0 * EDGE_DIM + i;
            eat[i] = (gi < M * EDGE_DIM) ? eattr[gi] : 0.f;
        }
        __syncthreads();

        for (int i = tid; i < TB * 64; i += 256) {
            int e = i >> 6, o = i & 63;
            float v = g_pa[(size_t)ssrc[e] * 64 + o] + g_pb[(size_t)sdst[e] * 64 + o]
                      + sdb1[o];
            #pragma unroll
            for (int k = 0; k < EDGE_DIM; k++) v += sw1c[k * 64 + o] * eat[e * EDGE_DIM + k];
            z1t[o * 34 + e] = fmaxf(v, 0.f);
        }
        __syncthreads();

        float b2a[2][2] = {{0.f, 0.f}, {0.f, 0.f}};
        #pragma unroll 4
        for (int k = 0; k < DEC_H1; k++) {
            float2 zv = *reinterpret_cast<const float2*>(&z1t[k * 34 + ty * 2]);
            float2 wv = *reinterpret_cast<const float2*>(&sw2[k * DEC_H2 + tx * 2]);
            b2a[0][0] += zv.x * wv.x; b2a[0][1] += zv.x * wv.y;
            b2a[1][0] += zv.y * wv.x; b2a[1][1] += zv.y * wv.y;
        }
        #pragma unroll
        for (int j = 0; j < 2; j++) {
            float b = sb2[tx * 2 + j];
            #pragma unroll
            for (int i = 0; i < 2; i++) {
                float v = b2a[i][j] + b;
                z2t[(tx * 2 + j) * 33 + ty * 2 + i] = fmaxf(v, 0.f);
            }
        }
        __syncthreads();

        if (tid < 128) {
            int e = tid >> 2, o = tid & 3;
            float acc = sb3[o];
            #pragma unroll
            for (int k = 0; k < DEC_H2; k++) acc += z2t[k * 33 + e] * sw3[o * DEC_H2 + k];
            if (e < nE) out[(e0 + e) * DEC_OUT + o] = acc;
        }
    }
}

// ---------------- launch -----------------------------------------------------
extern "C" void kernel_launch(void* const* d_in, const int* in_sizes, int n_in,
                              void* d_out, int out_size) {
    const float* x     = (const float*)d_in[0];
    const int*   ei    = (const int*)d_in[1];
    const float* eattr = (const float*)d_in[2];
    const float* u     = (const float*)d_in[3];
    const float* W1    = (const float*)d_in[4];
    const float* as1   = (const float*)d_in[5];
    const float* ad1   = (const float*)d_in[6];
    const float* b1    = (const float*)d_in[7];
    const float* W2    = (const float*)d_in[8];
    const float* as2   = (const float*)d_in[9];
    const float* ad2   = (const float*)d_in[10];
    const float* b2    = (const float*)d_in[11];
    const float* dw1   = (const float*)d_in[12];
    const float* db1   = (const float*)d_in[13];
    const float* dw2   = (const float*)d_in[14];
    const float* db2   = (const float*)d_in[15];
    const float* dw3   = (const float*)d_in[16];
    const float* db3   = (const float*)d_in[17];
    float* out = (float*)d_out;

    int N = in_sizes[0] / IN_NODE;
    int M = in_sizes[1] / 2;
    if (N > NMAX || M > EMAX || N <= 0 || M <= 0) return;

    const int* srcp = ei;
    const int* dstp = ei + M;
    int nb = (N + 1023) / 1024;

    k_zero<<<(N + 255) / 256, 256>>>(N);
    k_prep<<<1, 256>>>(u, W1, dw2);
    k_hist<<<(M + 255) / 256, 256>>>(dstp, M);
    k_scan1<<<nb, 1024>>>(N);
    k_scan2<<<1, 128>>>(nb, N, M);
    k_scan3<<<(N + 255) / 256, 256>>>(N);
    k_scatter<<<(M + 255) / 256, 256>>>(srcp, dstp, M);

    k_gemm1<<<(N + 3) / 4, 128>>>(x, as1, ad1, N);
    k_agg<<<N, 128>>>(b1, 1, N);

    k_gemm2<<<(N + G2N - 1) / G2N, 128>>>(W2, as2, ad2, N);
    k_agg<<<N, 128>>>(b2, 0, N);

    k_pab<<<(N + 15) / 16, 256>>>(dw1, N);
    k_dec<<<1184, 256>>>(ei, eattr, dw1, db1, db2, dw3, db3, out, M);
}

// round 4
// speedup vs baseline: 1.8839x; 1.0418x over previous
#include <cuda_runtime.h>
#include <math.h>

#define NMAX 100000
#define EMAX 1600000
#define HEADS 4
#define HID 32
#define F1 128
#define IN_NODE 12
#define IN_GLB 11
#define IN1 23
#define EDGE_DIM 5
#define DEC_IN 69
#define DEC_H1 64
#define DEC_H2 32
#define DEC_OUT 4

__device__ float g_g[NMAX * F1];
__device__ float g_h1[NMAX * F1];
__device__ float g_h2[NMAX * HID];
__device__ float g_pa[NMAX * DEC_H1];
__device__ float g_pb[NMAX * DEC_H1];
__device__ float g_als[NMAX * HEADS];
__device__ float g_ald[NMAX * HEADS];
__device__ int   g_cnt[NMAX];
__device__ int   g_off[NMAX + 1];
__device__ int   g_cur[NMAX];
__device__ int   g_srcs[EMAX];
__device__ int   g_bsum[128];
__device__ float g_t1[F1];
__device__ float g_w1tt[IN_NODE * F1];
__device__ float g_w2t[DEC_H1 * DEC_H2];

__device__ __forceinline__ float lrelu02(float x) { return x > 0.f ? x : 0.2f * x; }
__device__ __forceinline__ float eluf(float x)    { return x > 0.f ? x : expm1f(x); }

// ---- packed f32x2 helpers (sm_100+) ----------------------------------------
__device__ __forceinline__ unsigned long long pk2(float lo, float hi) {
    unsigned long long r;
    asm("mov.b64 %0, {%1, %2};" : "=l"(r) : "f"(lo), "f"(hi));
    return r;
}
__device__ __forceinline__ unsigned long long spl2(float v) { return pk2(v, v); }
__device__ __forceinline__ void fma2(unsigned long long& d, unsigned long long a,
                                     unsigned long long b) {
    asm("fma.rn.f32x2 %0, %1, %2, %0;" : "+l"(d) : "l"(a), "l"(b));
}
__device__ __forceinline__ float2 upk2(unsigned long long v) {
    float2 f;
    asm("mov.b64 {%0, %1}, %2;" : "=f"(f.x), "=f"(f.y) : "l"(v));
    return f;
}

// ---------------- prep ------------------------------------------------------
__global__ void k_prep(const float* __restrict__ u, const float* __restrict__ W1,
                       const float* __restrict__ dw2) {
    int tid = threadIdx.x;
    if (tid < F1) {
        float s = 0.f;
        #pragma unroll
        for (int k = 0; k < IN_GLB; k++) s += u[k] * W1[tid * IN1 + IN_NODE + k];
        g_t1[tid] = s;
    }
    for (int i = tid; i < IN_NODE * F1; i += blockDim.x) {
        int k = i >> 7, f = i & 127;
        g_w1tt[i] = W1[f * IN1 + k];
    }
    for (int i = tid; i < DEC_H1 * DEC_H2; i += blockDim.x) {
        int k = i >> 5, o = i & 31;
        g_w2t[i] = dw2[o * DEC_H1 + k];
    }
}

// ---------------- layer-1 node transform + attention logits ----------------
__global__ void k_gemm1(const float* __restrict__ x,
                        const float* __restrict__ asrc, const float* __restrict__ adst,
                        int N) {
    int n0 = blockIdx.x * 4;
    int f = threadIdx.x;
    __shared__ float xs[4][IN_NODE];
    if (f < 4 * IN_NODE) {
        int i = f / IN_NODE, k = f - i * IN_NODE;
        int n = n0 + i;
        xs[i][k] = (n < N) ? x[n * IN_NODE + k] : 0.f;
    }
    __syncthreads();
    float acc[4];
    float t = g_t1[f];
    #pragma unroll
    for (int i = 0; i < 4; i++) acc[i] = t;
    #pragma unroll
    for (int k = 0; k < IN_NODE; k++) {
        float w = g_w1tt[k * F1 + f];
        #pragma unroll
        for (int i = 0; i < 4; i++) acc[i] += xs[i][k] * w;
    }
    int h = f >> 5;
    float cas = asrc[f], cad = adst[f];
    #pragma unroll
    for (int i = 0; i < 4; i++) {
        int n = n0 + i;
        if (n >= N) break;
        g_g[n * F1 + f] = acc[i];
        float vs = acc[i] * cas, vd = acc[i] * cad;
        #pragma unroll
        for (int o = 16; o; o >>= 1) {
            vs += __shfl_xor_sync(0xffffffffu, vs, o);
            vd += __shfl_xor_sync(0xffffffffu, vd, o);
        }
        if ((f & 31) == 0) {
            g_als[n * HEADS + h] = vs;
            g_ald[n * HEADS + h] = vd;
        }
    }
}

// ---------------- layer-2 node transform (16 nodes/block, packed FMA) ------
#define G2N 16
__global__ __launch_bounds__(128) void k_gemm2(const float* __restrict__ W2,
                        const float* __restrict__ asrc, const float* __restrict__ adst,
                        int N) {
    int n0 = blockIdx.x * G2N;
    int f = threadIdx.x;
    __shared__ __align__(16) float hst[F1][G2N];   // k-major, node-minor
    #pragma unroll
    for (int i = 0; i < G2N; i++) {
        int n = n0 + i;
        hst[f][i] = (n < N) ? g_h1[n * F1 + f] : 0.f;
    }
    __syncthreads();
    unsigned long long acc2[8];
    #pragma unroll
    for (int p = 0; p < 8; p++) acc2[p] = 0ull;
    const float4* wrow = reinterpret_cast<const float4*>(W2 + f * F1);
    #pragma unroll 4
    for (int kq = 0; kq < F1 / 4; kq++) {
        float4 wv = wrow[kq];
        #pragma unroll
        for (int kk = 0; kk < 4; kk++) {
            float w = (kk == 0) ? wv.x : (kk == 1) ? wv.y : (kk == 2) ? wv.z : wv.w;
            unsigned long long ws = spl2(w);
            int k = kq * 4 + kk;
            const ulonglong2* hp = reinterpret_cast<const ulonglong2*>(&hst[k][0]);
            #pragma unroll
            for (int p = 0; p < 4; p++) {
                ulonglong2 hv = hp[p];
                fma2(acc2[p * 2], hv.x, ws);
                fma2(acc2[p * 2 + 1], hv.y, ws);
            }
        }
    }
    float acc[G2N];
    #pragma unroll
    for (int p = 0; p < 8; p++) {
        float2 t = upk2(acc2[p]);
        acc[p * 2] = t.x;
        acc[p * 2 + 1] = t.y;
    }
    int h = f >> 5;
    float cas = asrc[f], cad = adst[f];
    #pragma unroll
    for (int i = 0; i < G2N; i++) {
        int n = n0 + i;
        if (n >= N) break;
        g_g[n * F1 + f] = acc[i];
        float vs = acc[i] * cas, vd = acc[i] * cad;
        #pragma unroll
        for (int o = 16; o; o >>= 1) {
            vs += __shfl_xor_sync(0xffffffffu, vs, o);
            vd += __shfl_xor_sync(0xffffffffu, vd, o);
        }
        if ((f & 31) == 0) {
            g_als[n * HEADS + h] = vs;
            g_ald[n * HEADS + h] = vd;
        }
    }
}

// ---------------- CSR build --------------------------------------------------
__global__ void k_zero(int N) {
    int i = blockIdx.x * blockDim.x + threadIdx.x;
    if (i < N) g_cnt[i] = 0;
}
__global__ void k_hist(const int* __restrict__ dst, int M) {
    int e = blockIdx.x * blockDim.x + threadIdx.x;
    if (e < M) atomicAdd(&g_cnt[dst[e]], 1);
}
__global__ void k_scan1(int N) {
    __shared__ int sh[1024];
    int tid = threadIdx.x;
    int i = blockIdx.x * 1024 + tid;
    int v = (i < N) ? g_cnt[i] : 0;
    sh[tid] = v;
    __syncthreads();
    for (int o = 1; o < 1024; o <<= 1) {
        int t = (tid >= o) ? sh[tid - o] : 0;
        __syncthreads();
        sh[tid] += t;
        __syncthreads();
    }
    if (i < N) g_off[i] = sh[tid] - v;
    if (tid == 1023) g_bsum[blockIdx.x] = sh[1023];
}
// each block redundantly scans the (<=128) block sums, then adds + inits cur
__global__ void k_scan3(int nb, int N, int M) {
    __shared__ int sh[128];
    int tid = threadIdx.x;
    if (tid < 128) {
        int v = (tid < nb) ? g_bsum[tid] : 0;
        sh[tid] = v;
    }
    __syncthreads();
    if (tid < 128) {
        for (int o = 1; o < 128; o <<= 1) {
            int t = (tid >= o) ? sh[tid - o] : 0;
            __syncthreads();
            sh[tid] += t;
            __syncthreads();
        }
    } else {
        for (int o = 1; o < 128; o <<= 1) { __syncthreads(); __syncthreads(); }
    }
    int i = blockIdx.x * blockDim.x + tid;
    if (i < N) {
        int blk = i >> 10;
        int ex = (blk == 0) ? 0 : sh[blk - 1];
        int v = g_off[i] + ex;
        g_off[i] = v;
        g_cur[i] = v;
    }
    if (i == 0) g_off[N] = M;
}
__global__ void k_scatter(const int* __restrict__ src, const int* __restrict__ dst, int M) {
    int e = blockIdx.x * blockDim.x + threadIdx.x;
    if (e < M) {
        int d = dst[e];
        int p = atomicAdd(&g_cur[d], 1);
        g_srcs[p] = src[e];
    }
}

// ---------------- GAT aggregation: single pass ------------------------------
__global__ void k_agg(const float* __restrict__ bias, int concat, int N) {
    int n = blockIdx.x;
    if (n >= N) return;
    int h = threadIdx.x >> 5;
    int lane = threadIdx.x & 31;
    int beg = g_off[n], end = g_off[n + 1];

    float ad = g_ald[n * HEADS + h];
    float ws = __expf(lrelu02(g_als[n * HEADS + h] + ad));

    float acc = ws * g_g[n * F1 + (h << 5) + lane];
    float psum = 0.f;
    for (int base = beg; base < end; base += 32) {
        int j = base + lane;
        float w = 0.f;
        int s = 0;
        if (j < end) {
            s = g_srcs[j];
            w = __expf(lrelu02(g_als[s * HEADS + h] + ad));
            psum += w;
        }
        int lim = min(32, end - base);
        for (int kk = 0; kk < lim; kk++) {
            float wk = __shfl_sync(0xffffffffu, w, kk);
            int sk = __shfl_sync(0xffffffffu, s, kk);
            acc += wk * g_g[sk * F1 + (h << 5) + lane];
        }
    }
    #pragma unroll
    for (int o = 16; o; o >>= 1) psum += __shfl_xor_sync(0xffffffffu, psum, o);
    float v = acc / (psum + ws);

    if (concat) {
        v += bias[(h << 5) + lane];
        g_h1[n * F1 + (h << 5) + lane] = eluf(v);
    } else {
        __shared__ float sm[F1];
        sm[(h << 5) + lane] = v;
        __syncthreads();
        if (h == 0) {
            float t = (sm[lane] + sm[32 + lane] + sm[64 + lane] + sm[96 + lane]) * 0.25f
                      + bias[lane];
            g_h2[n * HID + lane] = eluf(t);
        }
    }
}

// ---------------- decoder precompute: pa/pb --------------------------------
__global__ __launch_bounds__(256) void k_pab(const float* __restrict__ dw1, int N) {
    __shared__ float sdw[64 * 65];
    __shared__ float sh2[16 * 32];
    int tid = threadIdx.x;
    for (int i = tid; i < 64 * 64; i += 256) {
        int o = i >> 6, k = i & 63;
        sdw[o * 65 + k] = dw1[o * DEC_IN + k];
    }
    int n0 = blockIdx.x * 16;
    for (int i = tid; i < 16 * 32; i += 256) {
        int nl = i >> 5, k = i & 31;
        int n = n0 + nl;
        sh2[i] = (n < N) ? g_h2[n * HID + k] : 0.f;
    }
    __syncthreads();
    int o = tid & 63, ng = tid >> 6;
    float pa[4] = {0.f, 0.f, 0.f, 0.f}, pb[4] = {0.f, 0.f, 0.f, 0.f};
    #pragma unroll
    for (int k = 0; k < 32; k++) {
        float wa = sdw[o * 65 + k];
        float wb = sdw[o * 65 + 32 + k];
        #pragma unroll
        for (int j = 0; j < 4; j++) {
            float hv = sh2[(ng * 4 + j) * 32 + k];
            pa[j] += wa * hv;
            pb[j] += wb * hv;
        }
    }
    #pragma unroll
    for (int j = 0; j < 4; j++) {
        int n = n0 + ng * 4 + j;
        if (n < N) {
            g_pa[n * 64 + o] = pa[j];
            g_pb[n * 64 + o] = pb[j];
        }
    }
}

// ---------------- decoder: 64-edge tiles, packed-FMA GEMM2 ------------------
#define TB 64
#define ZS (TB + 4)   // 68, float4-aligned stride
__global__ __launch_bounds__(256) void k_dec(
    const int* __restrict__ ei, const float* __restrict__ eattr,
    const float* __restrict__ dw1, const float* __restrict__ db1,
    const float* __restrict__ db2, const float* __restrict__ dw3,
    const float* __restrict__ db3, float* __restrict__ out, int M) {
    __shared__ __align__(16) float sw2[DEC_H1 * DEC_H2];   // [k][o]
    __shared__ float sw3[DEC_H2 * DEC_OUT];                // [o][k]
    __shared__ float sb2[DEC_H2];
    __shared__ float sb3[DEC_OUT];
    __shared__ float sw1c[EDGE_DIM * 64];
    __shared__ float sdb1[64];
    __shared__ int ssrc[TB], sdst[TB];
    __shared__ float eat[TB * EDGE_DIM];
    __shared__ __align__(16) float z1t[DEC_H1 * ZS];   // [k=64][e]
    __shared__ __align__(16) float z2t[DEC_H2 * ZS];   // [k=32][e]
    int tid = threadIdx.x;

    for (int i = tid; i < DEC_H1 * DEC_H2; i += 256) sw2[i] = g_w2t[i];
    if (tid < 128) sw3[tid] = dw3[tid];
    if (tid < 64)  sdb1[tid] = db1[tid];
    if (tid < 32)  sb2[tid] = db2[tid];
    if (tid < 4)   sb3[tid] = db3[tid];
    for (int i = tid; i < EDGE_DIM * 64; i += 256) {
        int k = i >> 6, o = i & 63;
        sw1c[i] = dw1[o * DEC_IN + 64 + k];
    }

    const int* srcp = ei;
    const int* dstp = ei + M;
    int ntiles = (M + TB - 1) / TB;
    int tx = tid & 15;       // o-group: o0 = tx*2
    int ty = tid >> 4;       // e-group: e0 = ty*4
    int o0 = tx * 2, e0 = ty * 4;

    for (int tile = blockIdx.x; tile < ntiles; tile += gridDim.x) {
        int eb = tile * TB;
        int nE = min(TB, M - eb);
        __syncthreads();
        if (tid < TB) {
            ssrc[tid] = (tid < nE) ? srcp[eb + tid] : 0;
            sdst[tid] = (tid < nE) ? dstp[eb + tid] : 0;
        }
        for (int i = tid; i < TB * EDGE_DIM; i += 256) {
            int gi = eb * EDGE_DIM + i;
            eat[i] = (gi < M * EDGE_DIM) ? eattr[gi] : 0.f;
        }
        __syncthreads();

        // z1[k=o][e] = relu(pa[src] + pb[dst] + dw1c@eattr + db1)
        for (int i = tid; i < TB * 64; i += 256) {
            int e = i >> 6, o = i & 63;
            float v = g_pa[(size_t)ssrc[e] * 64 + o] + g_pb[(size_t)sdst[e] * 64 + o]
                      + sdb1[o];
            #pragma unroll
            for (int k = 0; k < EDGE_DIM; k++) v += sw1c[k * 64 + o] * eat[e * EDGE_DIM + k];
            z1t[o * ZS + e] = fmaxf(v, 0.f);
        }
        __syncthreads();

        // GEMM2 packed: 4e x 2o per thread, K=64
        unsigned long long a00 = 0ull, a01 = 0ull, a10 = 0ull, a11 = 0ull;
        #pragma unroll 8
        for (int k = 0; k < DEC_H1; k++) {
            float4 zv = *reinterpret_cast<const float4*>(&z1t[k * ZS + e0]);
            float2 wv = *reinterpret_cast<const float2*>(&sw2[k * DEC_H2 + o0]);
            unsigned long long z01 = pk2(zv.x, zv.y);
            unsigned long long z23 = pk2(zv.z, zv.w);
            unsigned long long w0 = spl2(wv.x);
            unsigned long long w1 = spl2(wv.y);
            fma2(a00, z01, w0);
            fma2(a01, z01, w1);
            fma2(a10, z23, w0);
            fma2(a11, z23, w1);
        }
        {
            float b0 = sb2[o0], b1 = sb2[o0 + 1];
            float2 t00 = upk2(a00), t01 = upk2(a01), t10 = upk2(a10), t11 = upk2(a11);
            z2t[o0 * ZS + e0]           = fmaxf(t00.x + b0, 0.f);
            z2t[o0 * ZS + e0 + 1]       = fmaxf(t00.y + b0, 0.f);
            z2t[o0 * ZS + e0 + 2]       = fmaxf(t10.x + b0, 0.f);
            z2t[o0 * ZS + e0 + 3]       = fmaxf(t10.y + b0, 0.f);
            z2t[(o0 + 1) * ZS + e0]     = fmaxf(t01.x + b1, 0.f);
            z2t[(o0 + 1) * ZS + e0 + 1] = fmaxf(t01.y + b1, 0.f);
            z2t[(o0 + 1) * ZS + e0 + 2] = fmaxf(t11.x + b1, 0.f);
            z2t[(o0 + 1) * ZS + e0 + 3] = fmaxf(t11.y + b1, 0.f);
        }
        __syncthreads();

        // GEMM3: 64e x 4o, K=32; one output per thread
        {
            int e = tid & 63, o = tid >> 6;
            float acc = sb3[o];
            #pragma unroll
            for (int k = 0; k < DEC_H2; k++) acc += z2t[k * ZS + e] * sw3[o * DEC_H2 + k];
            if (e < nE) out[(eb + e) * DEC_OUT + o] = acc;
        }
    }
}

// ---------------- launch -----------------------------------------------------
extern "C" void kernel_launch(void* const* d_in, const int* in_sizes, int n_in,
                              void* d_out, int out_size) {
    const float* x     = (const float*)d_in[0];
    const int*   ei    = (const int*)d_in[1];
    const float* eattr = (const float*)d_in[2];
    const float* u     = (const float*)d_in[3];
    const float* W1    = (const float*)d_in[4];
    const float* as1   = (const float*)d_in[5];
    const float* ad1   = (const float*)d_in[6];
    const float* b1    = (const float*)d_in[7];
    const float* W2    = (const float*)d_in[8];
    const float* as2   = (const float*)d_in[9];
    const float* ad2   = (const float*)d_in[10];
    const float* b2    = (const float*)d_in[11];
    const float* dw1   = (const float*)d_in[12];
    const float* db1   = (const float*)d_in[13];
    const float* dw2   = (const float*)d_in[14];
    const float* db2   = (const float*)d_in[15];
    const float* dw3   = (const float*)d_in[16];
    const float* db3   = (const float*)d_in[17];
    float* out = (float*)d_out;

    int N = in_sizes[0] / IN_NODE;
    int M = in_sizes[1] / 2;
    if (N > NMAX || M > EMAX || N <= 0 || M <= 0) return;

    const int* srcp = ei;
    const int* dstp = ei + M;
    int nb = (N + 1023) / 1024;

    k_zero<<<(N + 255) / 256, 256>>>(N);
    k_prep<<<1, 256>>>(u, W1, dw2);
    k_hist<<<(M + 255) / 256, 256>>>(dstp, M);
    k_scan1<<<nb, 1024>>>(N);
    k_scan3<<<(N + 255) / 256, 256>>>(nb, N, M);
    k_scatter<<<(M + 255) / 256, 256>>>(srcp, dstp, M);

    k_gemm1<<<(N + 3) / 4, 128>>>(x, as1, ad1, N);
    k_agg<<<N, 128>>>(b1, 1, N);

    k_gemm2<<<(N + G2N - 1) / G2N, 128>>>(W2, as2, ad2, N);
    k_agg<<<N, 128>>>(b2, 0, N);

    k_pab<<<(N + 15) / 16, 256>>>(dw1, N);
    k_dec<<<1184, 256>>>(ei, eattr, dw1, db1, db2, dw3, db3, out, M);
}